// round 6
// baseline (speedup 1.0000x reference)
#include <cuda_runtime.h>
#include <math.h>

#define DTF       1e-4f
#define TSTEPS    4000000
#define SEG       8
#define TPB       256
#define STEPS_PER_CTA (SEG*TPB)                                /* 2048 */
#define NCTA      ((TSTEPS + STEPS_PER_CTA - 1)/STEPS_PER_CTA) /* 1954 */

// pass3 smem geometry (float4 units)
#define IN_ROW    7            /* 6 payload f4 + 1 pad (24 floats/seg) */
#define WARP_IN   (32*IN_ROW)  /* 224 f4 = 3584 B */
#define WARP_OUT  144          /* 16 rows x (8 payload f4 + 1 pad) = 2304 B */
#define P3_SMEM   (8*(WARP_IN+WARP_OUT)*16)   /* 47104 B */

struct SimConsts {
    float t00,t01,t10,t11;     // Trans
    float xi00,xi01,xi10,xi11; // XiCov
    float c00,c01,c10,c11;     // Cout
    float p0dt, p1, cA, sA;    // forcing scale, freq, per-step rotation
    float cA256, sA256;        // per-256-step rotation
    float x00, x01;            // initial state
    float Tpow[22][4];         // Tpow[r] = Trans^(2^r)
};
__device__ SimConsts gC;
__device__ float g_csum[NCTA*2];     // per-tile affine aggregate
__device__ float g_centry[NCTA*2];   // per-tile entry state

__device__ __forceinline__ void mat2mul(const float* a, const float* b, float* o) {
    o[0]=fmaf(a[0],b[0],a[1]*b[2]); o[1]=fmaf(a[0],b[1],a[1]*b[3]);
    o[2]=fmaf(a[2],b[0],a[3]*b[2]); o[3]=fmaf(a[2],b[1],a[3]*b[3]);
}

// ---------------------------------------------------------------- setup ----
__global__ void k_setup(const float* __restrict__ A, const float* __restrict__ B,
                        const float* __restrict__ E, const float* __restrict__ cov,
                        const float* __restrict__ tp, const float* __restrict__ ini)
{
    float a0=A[0],a1=A[1],a2=A[2],a3=A[3];
    float b0=B[0],b1=B[1],b2=B[2],b3=B[3];
    float e0=E[0],e1=E[1],e2=E[2],e3=E[3];
    float v0=cov[0],v1=cov[1],v2=cov[2],v3=cov[3];
    float s2 = sqrtf(2.0f);
    float cb0=fmaf(v0,b0,v1*b2), cb1=fmaf(v0,b1,v1*b3);
    float cb2=fmaf(v2,b0,v3*b2), cb3=fmaf(v2,b1,v3*b3);
    float xi0=(e0-cb0)/s2, xi1=(e1-cb1)/s2, xi2=(e2-cb2)/s2, xi3=(e3-cb3)/s2;
    float n0=-s2*b0, n1=-s2*b2, n2=-s2*b1, n3=-s2*b3;
    float xc0=fmaf(xi0,n0,xi1*n2), xc1=fmaf(xi0,n1,xi1*n3);
    float xc2=fmaf(xi2,n0,xi3*n2), xc3=fmaf(xi2,n1,xi3*n3);
    float tr[4] = { 1.0f + (a0-xc0)*DTF, (a1-xc1)*DTF,
                    (a2-xc2)*DTF, 1.0f + (a3-xc3)*DTF };
    gC.t00=tr[0]; gC.t01=tr[1]; gC.t10=tr[2]; gC.t11=tr[3];
    gC.xi00=xi0; gC.xi01=xi1; gC.xi10=xi2; gC.xi11=xi3;
    gC.c00=n0*DTF; gC.c01=n1*DTF; gC.c10=n2*DTF; gC.c11=n3*DTF;
    gC.p0dt = tp[0]*DTF;
    gC.p1   = tp[1];
    double pd = (double)tp[1] * 1e-4;
    gC.cA = (float)cos(pd);          gC.sA = (float)sin(pd);
    gC.cA256 = (float)cos(pd*256.0); gC.sA256 = (float)sin(pd*256.0);
    gC.x00 = ini[0]; gC.x01 = ini[1];
    for (int i=0;i<4;i++) gC.Tpow[0][i]=tr[i];
    for (int r=1;r<22;r++) mat2mul(gC.Tpow[r-1], gC.Tpow[r-1], gC.Tpow[r]);
}

// One simulated step: update state (x0,x1) with forcing rotation (cc,ss).
#define UPSTATE(d0,d1) do{                                            \
    float a0_ = fmaf(xi01,(d1),cc);  a0_ = fmaf(xi00,(d0),a0_);        \
    float a1_ = xi11*(d1);           a1_ = fmaf(xi10,(d0),a1_);        \
    float nx0_ = fmaf(t01,x1,a0_);   nx0_ = fmaf(t00,x0,nx0_);         \
    float nx1_ = fmaf(t11,x1,a1_);   nx1_ = fmaf(t10,x0,nx1_);         \
    x0=nx0_; x1=nx1_;                                                  \
    float nc_ = fmaf(cc,cA,-(ss*sA)); ss = fmaf(ss,cA,cc*sA); cc=nc_;  \
} while(0)

#define OUTPAIR(o0,o1) do{ (o0)=fmaf(c00,x0,c01*x1); (o1)=fmaf(c10,x0,c11*x1); }while(0)

// ---------------------------------------------------------------- pass1 ----
// Lean aggregate-only pass. Thread t owns strided steps 256j+t (coalesced).
// c_tile = sum_t M^(255-t) * sum_j (M^256)^(7-j) * b_(256j+t)
__global__ void __launch_bounds__(TPB) k_pass1(const float* __restrict__ in)
{
    __shared__ float2 swarp[8];
    const int tid = threadIdx.x, blk = blockIdx.x;
    const int lane = tid & 31, wid = tid >> 5;
    const int base = blk*STEPS_PER_CTA;

    const float xi00=gC.xi00,xi01=gC.xi01,xi10=gC.xi10,xi11=gC.xi11;
    const float M0=gC.Tpow[8][0],M1=gC.Tpow[8][1],M2=gC.Tpow[8][2],M3=gC.Tpow[8][3];
    const float cR=gC.cA256, sR=gC.sA256, p0dt=gC.p0dt, p1=gC.p1;

    // forcing: t_k = k*dt in fp32 matches the stored t channel bit-exactly
    float sv,cv; sincosf(p1 * ((float)(base+tid)*DTF), &sv,&cv);
    float cc = p0dt*cv, ss = p0dt*sv;

    float S0=0.f, S1=0.f;
    const float* p = in + (size_t)base*3 + tid*3;
    #pragma unroll
    for (int j=0;j<8;j++){
        int k = base + 256*j + tid;
        float b0=0.f, b1=0.f;
        if (k < TSTEPS){
            float d0 = p[768*j+1];
            float d1 = p[768*j+2];
            b0 = fmaf(xi00,d0, fmaf(xi01,d1, cc));
            b1 = fmaf(xi10,d0, xi11*d1);
        }
        float n0 = fmaf(M0,S0, fmaf(M1,S1, b0));
        float n1 = fmaf(M2,S0, fmaf(M3,S1, b1));
        S0=n0; S1=n1;
        float nc = fmaf(cc,cR,-(ss*sR)); ss = fmaf(ss,cR,cc*sR); cc=nc;
    }

    // in-warp weighted butterfly: R <- M^(2^r)*R + R[lane+2^r]
    #pragma unroll
    for (int r=0;r<5;r++){
        float u0=__shfl_down_sync(0xffffffffu,S0,1<<r);
        float u1=__shfl_down_sync(0xffffffffu,S1,1<<r);
        float P0=gC.Tpow[r][0],P1=gC.Tpow[r][1],P2=gC.Tpow[r][2],P3=gC.Tpow[r][3];
        float n0 = fmaf(P0,S0, fmaf(P1,S1, u0));
        float n1 = fmaf(P2,S0, fmaf(P3,S1, u1));
        S0=n0; S1=n1;
    }
    if (lane==0) swarp[wid] = make_float2(S0,S1);
    __syncthreads();
    if (wid==0 && lane<8){
        float2 R = swarp[lane];
        float R0=R.x, R1=R.y;
        #pragma unroll
        for (int r=0;r<3;r++){
            float u0=__shfl_down_sync(0x000000ffu,R0,1<<r);
            float u1=__shfl_down_sync(0x000000ffu,R1,1<<r);
            float P0=gC.Tpow[5+r][0],P1=gC.Tpow[5+r][1],P2=gC.Tpow[5+r][2],P3=gC.Tpow[5+r][3];
            float n0 = fmaf(P0,R0, fmaf(P1,R1, u0));
            float n1 = fmaf(P2,R0, fmaf(P3,R1, u1));
            R0=n0; R1=n1;
        }
        if (lane==0){ g_csum[2*blk]=R0; g_csum[2*blk+1]=R1; }
    }
}

// ---------------------------------------------------------------- pass2 ----
// 1024 threads; thread g owns the tile PAIR (2g, 2g+1).
__global__ void k_pass2()
{
    const int g = threadIdx.x;
    __shared__ float sa[1024], sb[1024];
    const int u0i = 2*g, u1i = 2*g+1;
    float a00 = (u0i<NCTA)? g_csum[2*u0i]   : 0.f;
    float a01 = (u0i<NCTA)? g_csum[2*u0i+1] : 0.f;
    float a10 = (u1i<NCTA)? g_csum[2*u1i]   : 0.f;
    float a11 = (u1i<NCTA)? g_csum[2*u1i+1] : 0.f;
    const float Tc0=gC.Tpow[11][0],Tc1=gC.Tpow[11][1],Tc2=gC.Tpow[11][2],Tc3=gC.Tpow[11][3];
    float v0 = fmaf(Tc0,a00,fmaf(Tc1,a01,a10));   // pair offset
    float v1 = fmaf(Tc2,a00,fmaf(Tc3,a01,a11));
    sa[g]=v0; sb[g]=v1;
    __syncthreads();
    #pragma unroll
    for (int r=0;r<10;r++){
        int off = 1<<r;
        float w0=0.f, w1=0.f;
        if (g>=off){ w0=sa[g-off]; w1=sb[g-off]; }
        __syncthreads();
        float P0=gC.Tpow[12+r][0],P1=gC.Tpow[12+r][1],P2=gC.Tpow[12+r][2],P3=gC.Tpow[12+r][3];
        v0 = fmaf(P0,w0,fmaf(P1,w1,v0));
        v1 = fmaf(P2,w0,fmaf(P3,w1,v1));
        sa[g]=v0; sb[g]=v1;
        __syncthreads();
    }
    float e0 = g ? sa[g-1] : 0.f;
    float e1 = g ? sb[g-1] : 0.f;
    // + (M^4096)^g * x0
    float X0=gC.x00, X1=gC.x01;
    #pragma unroll
    for (int r=0;r<10;r++) if ((g>>r)&1){
        float P0=gC.Tpow[12+r][0],P1=gC.Tpow[12+r][1],P2=gC.Tpow[12+r][2],P3=gC.Tpow[12+r][3];
        float n0=fmaf(P0,X0,P1*X1), n1=fmaf(P2,X0,P3*X1);
        X0=n0; X1=n1;
    }
    float E0 = e0 + X0, E1 = e1 + X1;          // entry of tile 2g
    if (u0i<NCTA){ g_centry[2*u0i]=E0; g_centry[2*u0i+1]=E1; }
    if (u1i<NCTA){
        g_centry[2*u1i]   = fmaf(Tc0,E0,fmaf(Tc1,E1,a00));
        g_centry[2*u1i+1] = fmaf(Tc2,E0,fmaf(Tc3,E1,a01));
    }
}

// ---------------------------------------------------------------- pass3 ----
__global__ void __launch_bounds__(TPB) k_pass3(const float* __restrict__ in,
                                               float* __restrict__ out)
{
    extern __shared__ float4 s4[];
    __shared__ float sa[TPB], sb[TPB];
    const int tid = threadIdx.x, blk = blockIdx.x;
    const int lane = tid & 31, wid = tid >> 5;

    const float t00=gC.t00,t01=gC.t01,t10=gC.t10,t11=gC.t11;
    const float xi00=gC.xi00,xi01=gC.xi01,xi10=gC.xi10,xi11=gC.xi11;
    const float c00=gC.c00,c01=gC.c01,c10=gC.c10,c11=gC.c11;
    const float cA=gC.cA, sA=gC.sA, p0dt=gC.p0dt, p1=gC.p1;

    const int warpStepBase = blk*STEPS_PER_CTA + wid*32*SEG;
    const bool wfull = (warpStepBase + 32*SEG <= TSTEPS);
    float4* sin4  = s4 + wid*WARP_IN;
    float4* sout4 = s4 + 8*WARP_IN + wid*WARP_OUT;

    float Ew0 = g_centry[2*blk], Ew1 = g_centry[2*blk+1];

    // ---- stage input (streaming) ----
    if (wfull){
        const float4* p4 = (const float4*)in + (size_t)warpStepBase*3/4;
        #pragma unroll
        for (int i=0;i<6;i++){
            int q = lane + 32*i;
            float4 v = __ldcs(p4+q);
            int to = q/6, c = q - to*6;
            sin4[to*IN_ROW + c] = v;
        }
    }
    __syncwarp();

    // ---- offset pass: run 8 steps from x=0 ----
    float cc0=0.f, ss0=0.f, o0=0.f, o1=0.f;
    if (wfull){
        const float4* row = sin4 + lane*IN_ROW;
        float x0=0.f, x1=0.f;
        float sv,cv; sincosf(p1*row[0].x,&sv,&cv);
        cc0=p0dt*cv; ss0=p0dt*sv;
        float cc=cc0, ss=ss0;
        #pragma unroll
        for (int j=0;j<2;j++){
            float4 a=row[3*j], b=row[3*j+1], c=row[3*j+2];
            UPSTATE(a.y,a.z);
            UPSTATE(b.x,b.y);
            UPSTATE(b.w,c.x);
            UPSTATE(c.z,c.w);
        }
        o0=x0; o1=x1;
    }

    // ---- CTA Kogge-Stone over per-thread offsets ----
    float v0=o0, v1=o1;
    sa[tid]=v0; sb[tid]=v1;
    __syncthreads();
    #pragma unroll
    for (int r=0;r<8;r++){
        int off = 1<<r;
        float u0=0.f, u1=0.f;
        if (tid>=off){ u0=sa[tid-off]; u1=sb[tid-off]; }
        __syncthreads();
        float P0=gC.Tpow[3+r][0],P1=gC.Tpow[3+r][1],P2=gC.Tpow[3+r][2],P3=gC.Tpow[3+r][3];
        v0 = fmaf(P0,u0,fmaf(P1,u1,v0));
        v1 = fmaf(P2,u0,fmaf(P3,u1,v1));
        sa[tid]=v0; sb[tid]=v1;
        __syncthreads();
    }
    float ex0 = tid ? sa[tid-1] : 0.f;
    float ex1 = tid ? sb[tid-1] : 0.f;

    // ---- per-thread entry = (M^8)^tid * tile_entry + exclusive prefix ----
    float X0=Ew0, X1=Ew1;
    #pragma unroll
    for (int r=0;r<8;r++) if ((tid>>r)&1){
        float P0=gC.Tpow[3+r][0],P1=gC.Tpow[3+r][1],P2=gC.Tpow[3+r][2],P3=gC.Tpow[3+r][3];
        float n0=fmaf(P0,X0,P1*X1), n1=fmaf(P2,X0,P3*X1);
        X0=n0; X1=n1;
    }
    float x0 = X0 + ex0;
    float x1 = X1 + ex1;

    // ---- replay with outputs ----
    if (wfull){
        const float4* row  = sin4 + lane*IN_ROW;
        float4*       orow = sout4 + (lane>>1)*9 + (lane&1)*4;
        float cc=cc0, ss=ss0;
        #pragma unroll
        for (int j=0;j<2;j++){
            float4 a=row[3*j], b=row[3*j+1], c=row[3*j+2];
            float4 O0, O1;
            OUTPAIR(O0.x,O0.y); UPSTATE(a.y,a.z);
            OUTPAIR(O0.z,O0.w); UPSTATE(b.x,b.y);
            OUTPAIR(O1.x,O1.y); UPSTATE(b.w,c.x);
            OUTPAIR(O1.z,O1.w); UPSTATE(c.z,c.w);
            orow[2*j]   = O0;
            orow[2*j+1] = O1;
        }
        __syncwarp();
        float4* q4 = (float4*)out + (size_t)warpStepBase/2;
        #pragma unroll
        for (int i=0;i<4;i++){
            int q = lane + 32*i;
            __stcs(q4+q, sout4[(q>>3)*9 + (q&7)]);
        }
    }
}

// --------------------------------------------------------------- launch ----
extern "C" void kernel_launch(void* const* d_in, const int* in_sizes, int n_in,
                              void* d_out, int out_size)
{
    const float* in  = (const float*)d_in[0];
    const float* A   = (const float*)d_in[1];
    const float* B   = (const float*)d_in[2];
    // d_in[3] = D (unused by the reference)
    const float* E   = (const float*)d_in[4];
    const float* cov = (const float*)d_in[5];
    const float* tp  = (const float*)d_in[6];
    const float* ini = (const float*)d_in[7];
    float* out = (float*)d_out;

    cudaFuncSetAttribute(k_pass3, cudaFuncAttributeMaxDynamicSharedMemorySize, P3_SMEM);

    k_setup<<<1,1>>>(A,B,E,cov,tp,ini);
    k_pass1<<<NCTA,TPB>>>(in);
    k_pass2<<<1,1024>>>();
    k_pass3<<<NCTA,TPB,P3_SMEM>>>(in, out);
}

// round 7
// speedup vs baseline: 1.1030x; 1.1030x over previous
#include <cuda_runtime.h>
#include <math.h>

#define DTF       1e-4f
#define TSTEPS    4000000
#define SEG       8
#define TPB       256
#define STEPS_PER_CTA (SEG*TPB)                                /* 2048 */
#define NCTA      ((TSTEPS + STEPS_PER_CTA - 1)/STEPS_PER_CTA) /* 1954 */

// pass3 smem geometry (float4 units)
#define IN_ROW    7            /* 6 payload f4 + 1 pad (24 floats/seg) */
#define WARP_IN   (32*IN_ROW)  /* 224 f4 = 3584 B */
#define WARP_OUT  144          /* 16 rows x (8 payload f4 + 1 pad) = 2304 B */
#define P3_SMEM   (8*(WARP_IN+WARP_OUT)*16)   /* 47104 B */

struct SimConsts {
    float t00,t01,t10,t11;     // Trans
    float xi00,xi01,xi10,xi11; // XiCov
    float c00,c01,c10,c11;     // Cout
    float p0dt, p1, cA, sA;    // forcing scale, freq, per-step rotation
    float cA32, sA32;          // per-32-step rotation
    float x00, x01;            // initial state
    float Tpow[22][4];         // Tpow[r] = Trans^(2^r)
};
__device__ SimConsts gC;
__device__ float2 g_wagg[NCTA*8];    // per-warp (256-step) affine aggregate
__device__ float  g_csum[NCTA*2];    // per-tile affine aggregate
__device__ float  g_centry[NCTA*2];  // per-tile entry state

__device__ __forceinline__ void mat2mul(const float* a, const float* b, float* o) {
    o[0]=fmaf(a[0],b[0],a[1]*b[2]); o[1]=fmaf(a[0],b[1],a[1]*b[3]);
    o[2]=fmaf(a[2],b[0],a[3]*b[2]); o[3]=fmaf(a[2],b[1],a[3]*b[3]);
}

// ---------------------------------------------------------------- setup ----
__global__ void k_setup(const float* __restrict__ A, const float* __restrict__ B,
                        const float* __restrict__ E, const float* __restrict__ cov,
                        const float* __restrict__ tp, const float* __restrict__ ini)
{
    float a0=A[0],a1=A[1],a2=A[2],a3=A[3];
    float b0=B[0],b1=B[1],b2=B[2],b3=B[3];
    float e0=E[0],e1=E[1],e2=E[2],e3=E[3];
    float v0=cov[0],v1=cov[1],v2=cov[2],v3=cov[3];
    float s2 = sqrtf(2.0f);
    float cb0=fmaf(v0,b0,v1*b2), cb1=fmaf(v0,b1,v1*b3);
    float cb2=fmaf(v2,b0,v3*b2), cb3=fmaf(v2,b1,v3*b3);
    float xi0=(e0-cb0)/s2, xi1=(e1-cb1)/s2, xi2=(e2-cb2)/s2, xi3=(e3-cb3)/s2;
    float n0=-s2*b0, n1=-s2*b2, n2=-s2*b1, n3=-s2*b3;
    float xc0=fmaf(xi0,n0,xi1*n2), xc1=fmaf(xi0,n1,xi1*n3);
    float xc2=fmaf(xi2,n0,xi3*n2), xc3=fmaf(xi2,n1,xi3*n3);
    float tr[4] = { 1.0f + (a0-xc0)*DTF, (a1-xc1)*DTF,
                    (a2-xc2)*DTF, 1.0f + (a3-xc3)*DTF };
    gC.t00=tr[0]; gC.t01=tr[1]; gC.t10=tr[2]; gC.t11=tr[3];
    gC.xi00=xi0; gC.xi01=xi1; gC.xi10=xi2; gC.xi11=xi3;
    gC.c00=n0*DTF; gC.c01=n1*DTF; gC.c10=n2*DTF; gC.c11=n3*DTF;
    gC.p0dt = tp[0]*DTF;
    gC.p1   = tp[1];
    double pd = (double)tp[1] * 1e-4;
    gC.cA = (float)cos(pd);         gC.sA = (float)sin(pd);
    gC.cA32 = (float)cos(pd*32.0);  gC.sA32 = (float)sin(pd*32.0);
    gC.x00 = ini[0]; gC.x01 = ini[1];
    for (int i=0;i<4;i++) gC.Tpow[0][i]=tr[i];
    for (int r=1;r<22;r++) mat2mul(gC.Tpow[r-1], gC.Tpow[r-1], gC.Tpow[r]);
}

// One simulated step: update state (x0,x1) with forcing rotation (cc,ss).
#define UPSTATE(d0,d1) do{                                            \
    float a0_ = fmaf(xi01,(d1),cc);  a0_ = fmaf(xi00,(d0),a0_);        \
    float a1_ = xi11*(d1);           a1_ = fmaf(xi10,(d0),a1_);        \
    float nx0_ = fmaf(t01,x1,a0_);   nx0_ = fmaf(t00,x0,nx0_);         \
    float nx1_ = fmaf(t11,x1,a1_);   nx1_ = fmaf(t10,x0,nx1_);         \
    x0=nx0_; x1=nx1_;                                                  \
    float nc_ = fmaf(cc,cA,-(ss*sA)); ss = fmaf(ss,cA,cc*sA); cc=nc_;  \
} while(0)

// ---------------------------------------------------------------- pass1 ----
// Per-warp lean aggregates. Warp owns 256 contiguous steps; lane owns steps
// 32j+lane (coalesced). W = sum_lane M^(31-lane) * sum_j (M^32)^(7-j) b_(32j+lane)
__global__ void __launch_bounds__(TPB) k_pass1(const float* __restrict__ in)
{
    __shared__ float2 swarp[8];
    const int tid = threadIdx.x, blk = blockIdx.x;
    const int lane = tid & 31, wid = tid >> 5;
    const int warpBase = blk*STEPS_PER_CTA + wid*256;

    const float xi00=gC.xi00,xi01=gC.xi01,xi10=gC.xi10,xi11=gC.xi11;
    const float M0=gC.Tpow[5][0],M1=gC.Tpow[5][1],M2=gC.Tpow[5][2],M3=gC.Tpow[5][3];
    const float cR=gC.cA32, sR=gC.sA32, p0dt=gC.p0dt, p1=gC.p1;

    float sv,cv; sincosf(p1 * ((float)(warpBase+lane)*DTF), &sv,&cv);
    float cc = p0dt*cv, ss = p0dt*sv;

    float S0=0.f, S1=0.f;
    const float* p = in + (size_t)warpBase*3 + lane*3;
    #pragma unroll
    for (int j=0;j<8;j++){
        int k = warpBase + 32*j + lane;
        float b0=0.f, b1=0.f;
        if (k < TSTEPS){
            float d0 = p[96*j+1];
            float d1 = p[96*j+2];
            b0 = fmaf(xi00,d0, fmaf(xi01,d1, cc));
            b1 = fmaf(xi10,d0, xi11*d1);
        }
        float n0 = fmaf(M0,S0, fmaf(M1,S1, b0));
        float n1 = fmaf(M2,S0, fmaf(M3,S1, b1));
        S0=n0; S1=n1;
        float nc = fmaf(cc,cR,-(ss*sR)); ss = fmaf(ss,cR,cc*sR); cc=nc;
    }

    // in-warp weighted butterfly: R <- M^(2^r)*R + R[lane+2^r]
    #pragma unroll
    for (int r=0;r<5;r++){
        float u0=__shfl_down_sync(0xffffffffu,S0,1<<r);
        float u1=__shfl_down_sync(0xffffffffu,S1,1<<r);
        float P0=gC.Tpow[r][0],P1=gC.Tpow[r][1],P2=gC.Tpow[r][2],P3=gC.Tpow[r][3];
        float n0 = fmaf(P0,S0, fmaf(P1,S1, u0));
        float n1 = fmaf(P2,S0, fmaf(P3,S1, u1));
        S0=n0; S1=n1;
    }
    if (lane==0){
        g_wagg[blk*8+wid] = make_float2(S0,S1);
        swarp[wid] = make_float2(S0,S1);
    }
    __syncthreads();
    if (wid==0 && lane<8){
        float2 R = swarp[lane];
        float R0=R.x, R1=R.y;
        #pragma unroll
        for (int r=0;r<3;r++){
            float u0=__shfl_down_sync(0x000000ffu,R0,1<<r);
            float u1=__shfl_down_sync(0x000000ffu,R1,1<<r);
            float P0=gC.Tpow[8+r][0],P1=gC.Tpow[8+r][1],P2=gC.Tpow[8+r][2],P3=gC.Tpow[8+r][3];
            float n0 = fmaf(P0,R0, fmaf(P1,R1, u0));
            float n1 = fmaf(P2,R0, fmaf(P3,R1, u1));
            R0=n0; R1=n1;
        }
        if (lane==0){ g_csum[2*blk]=R0; g_csum[2*blk+1]=R1; }
    }
}

// ---------------------------------------------------------------- pass2 ----
// 1024 threads; thread g owns the tile PAIR (2g, 2g+1).
__global__ void k_pass2()
{
    const int g = threadIdx.x;
    __shared__ float sa[1024], sb[1024];
    const int u0i = 2*g, u1i = 2*g+1;
    float a00 = (u0i<NCTA)? g_csum[2*u0i]   : 0.f;
    float a01 = (u0i<NCTA)? g_csum[2*u0i+1] : 0.f;
    float a10 = (u1i<NCTA)? g_csum[2*u1i]   : 0.f;
    float a11 = (u1i<NCTA)? g_csum[2*u1i+1] : 0.f;
    const float Tc0=gC.Tpow[11][0],Tc1=gC.Tpow[11][1],Tc2=gC.Tpow[11][2],Tc3=gC.Tpow[11][3];
    float v0 = fmaf(Tc0,a00,fmaf(Tc1,a01,a10));   // pair offset
    float v1 = fmaf(Tc2,a00,fmaf(Tc3,a01,a11));
    sa[g]=v0; sb[g]=v1;
    __syncthreads();
    #pragma unroll
    for (int r=0;r<10;r++){
        int off = 1<<r;
        float w0=0.f, w1=0.f;
        if (g>=off){ w0=sa[g-off]; w1=sb[g-off]; }
        __syncthreads();
        float P0=gC.Tpow[12+r][0],P1=gC.Tpow[12+r][1],P2=gC.Tpow[12+r][2],P3=gC.Tpow[12+r][3];
        v0 = fmaf(P0,w0,fmaf(P1,w1,v0));
        v1 = fmaf(P2,w0,fmaf(P3,w1,v1));
        sa[g]=v0; sb[g]=v1;
        __syncthreads();
    }
    float e0 = g ? sa[g-1] : 0.f;
    float e1 = g ? sb[g-1] : 0.f;
    // + (M^4096)^g * x0
    float X0=gC.x00, X1=gC.x01;
    #pragma unroll
    for (int r=0;r<10;r++) if ((g>>r)&1){
        float P0=gC.Tpow[12+r][0],P1=gC.Tpow[12+r][1],P2=gC.Tpow[12+r][2],P3=gC.Tpow[12+r][3];
        float n0=fmaf(P0,X0,P1*X1), n1=fmaf(P2,X0,P3*X1);
        X0=n0; X1=n1;
    }
    float E0 = e0 + X0, E1 = e1 + X1;          // entry of tile 2g
    if (u0i<NCTA){ g_centry[2*u0i]=E0; g_centry[2*u0i+1]=E1; }
    if (u1i<NCTA){
        g_centry[2*u1i]   = fmaf(Tc0,E0,fmaf(Tc1,E1,a00));
        g_centry[2*u1i+1] = fmaf(Tc2,E0,fmaf(Tc3,E1,a01));
    }
}

// ---------------------------------------------------------------- pass3 ----
// Zero CTA barriers: all scan work is warp-local (shuffles).
__global__ void __launch_bounds__(TPB,4) k_pass3(const float* __restrict__ in,
                                                 float* __restrict__ out)
{
    extern __shared__ float4 s4[];
    const int tid = threadIdx.x, blk = blockIdx.x;
    const int lane = tid & 31, wid = tid >> 5;

    const float t00=gC.t00,t01=gC.t01,t10=gC.t10,t11=gC.t11;
    const float xi00=gC.xi00,xi01=gC.xi01,xi10=gC.xi10,xi11=gC.xi11;
    const float c00=gC.c00,c01=gC.c01,c10=gC.c10,c11=gC.c11;
    const float cA=gC.cA, sA=gC.sA, p0dt=gC.p0dt, p1=gC.p1;

    const int warpStepBase = blk*STEPS_PER_CTA + wid*256;
    const bool wfull = (warpStepBase + 256 <= TSTEPS);
    if (!wfull) return;

    float4* sin4  = s4 + wid*WARP_IN;
    float4* sout4 = s4 + 8*WARP_IN + wid*WARP_OUT;

    // ---- warp entry: E_w = (M^256)^wid * tile_entry + prefix of warp aggs ----
    float We0, We1;
    {
        float w0=0.f, w1=0.f;
        if (lane < 8){ float2 wa = g_wagg[blk*8+lane]; w0=wa.x; w1=wa.y; }
        // inclusive 8-lane KS, matrices (M^256)^(2^r)
        #pragma unroll
        for (int r=0;r<3;r++){
            int off = 1<<r;
            float u0=__shfl_up_sync(0xffffffffu,w0,off);
            float u1=__shfl_up_sync(0xffffffffu,w1,off);
            if (lane>=off){
                float P0=gC.Tpow[8+r][0],P1=gC.Tpow[8+r][1],P2=gC.Tpow[8+r][2],P3=gC.Tpow[8+r][3];
                w0 = fmaf(P0,u0,fmaf(P1,u1,w0));
                w1 = fmaf(P2,u0,fmaf(P3,u1,w1));
            }
        }
        float pf0=__shfl_up_sync(0xffffffffu,w0,1);
        float pf1=__shfl_up_sync(0xffffffffu,w1,1);
        if (lane==0){ pf0=0.f; pf1=0.f; }
        // (M^256)^lane * tile_entry
        float X0=g_centry[2*blk], X1=g_centry[2*blk+1];
        #pragma unroll
        for (int r=0;r<3;r++) if ((lane>>r)&1){
            float P0=gC.Tpow[8+r][0],P1=gC.Tpow[8+r][1],P2=gC.Tpow[8+r][2],P3=gC.Tpow[8+r][3];
            float n0=fmaf(P0,X0,P1*X1), n1=fmaf(P2,X0,P3*X1);
            X0=n0; X1=n1;
        }
        float e0 = X0 + pf0, e1 = X1 + pf1;
        We0 = __shfl_sync(0xffffffffu, e0, wid);
        We1 = __shfl_sync(0xffffffffu, e1, wid);
    }

    // ---- stage input (streaming, coalesced -> padded rows) ----
    const float4* p4 = (const float4*)in + (size_t)warpStepBase*3/4;
    #pragma unroll
    for (int i=0;i<6;i++){
        int q = lane + 32*i;
        float4 v = __ldcs(p4+q);
        int to = q/6, c = q - to*6;
        sin4[to*IN_ROW + c] = v;
    }
    __syncwarp();

    // ---- offset pass from x=0, recording intermediate offset states ----
    float ox[8], oy[8];
    float x0=0.f, x1=0.f;
    {
        const float4* row = sin4 + lane*IN_ROW;
        float4 a0v=row[0], b0v=row[1], c0v=row[2];
        float4 a1v=row[3], b1v=row[4], c1v=row[5];
        float sv,cv; sincosf(p1*a0v.x,&sv,&cv);
        float cc=p0dt*cv, ss=p0dt*sv;
        ox[0]=0.f;  oy[0]=0.f;   UPSTATE(a0v.y,a0v.z);
        ox[1]=x0;   oy[1]=x1;    UPSTATE(b0v.x,b0v.y);
        ox[2]=x0;   oy[2]=x1;    UPSTATE(b0v.w,c0v.x);
        ox[3]=x0;   oy[3]=x1;    UPSTATE(c0v.z,c0v.w);
        ox[4]=x0;   oy[4]=x1;    UPSTATE(a1v.y,a1v.z);
        ox[5]=x0;   oy[5]=x1;    UPSTATE(b1v.x,b1v.y);
        ox[6]=x0;   oy[6]=x1;    UPSTATE(b1v.w,c1v.x);
        ox[7]=x0;   oy[7]=x1;    UPSTATE(c1v.z,c1v.w);
    }

    // ---- warp KS over per-lane offsets (segment = 8 steps) ----
    float v0=x0, v1=x1;
    #pragma unroll
    for (int r=0;r<5;r++){
        int off = 1<<r;
        float u0=__shfl_up_sync(0xffffffffu,v0,off);
        float u1=__shfl_up_sync(0xffffffffu,v1,off);
        if (lane>=off){
            float P0=gC.Tpow[3+r][0],P1=gC.Tpow[3+r][1],P2=gC.Tpow[3+r][2],P3=gC.Tpow[3+r][3];
            v0 = fmaf(P0,u0,fmaf(P1,u1,v0));
            v1 = fmaf(P2,u0,fmaf(P3,u1,v1));
        }
    }
    float ex0=__shfl_up_sync(0xffffffffu,v0,1);
    float ex1=__shfl_up_sync(0xffffffffu,v1,1);
    if (lane==0){ ex0=0.f; ex1=0.f; }

    // ---- thread entry = (M^8)^lane * warp_entry + exclusive prefix ----
    float e0=We0, e1=We1;
    #pragma unroll
    for (int r=0;r<5;r++) if ((lane>>r)&1){
        float P0=gC.Tpow[3+r][0],P1=gC.Tpow[3+r][1],P2=gC.Tpow[3+r][2],P3=gC.Tpow[3+r][3];
        float n0=fmaf(P0,e0,P1*e1), n1=fmaf(P2,e0,P3*e1);
        e0=n0; e1=n1;
    }
    e0 += ex0; e1 += ex1;

    // ---- outputs: x_k = M^k * E + o_k ; out_k = C x_k ----
    {
        float4* orow = sout4 + (lane>>1)*9 + (lane&1)*4;
        float E0=e0, E1=e1;
        #pragma unroll
        for (int j=0;j<4;j++){
            float4 O;
            float xk0 = E0 + ox[2*j],   xk1 = E1 + oy[2*j];
            O.x = fmaf(c00,xk0,c01*xk1); O.y = fmaf(c10,xk0,c11*xk1);
            { float n0=fmaf(t00,E0,t01*E1), n1=fmaf(t10,E0,t11*E1); E0=n0; E1=n1; }
            xk0 = E0 + ox[2*j+1]; xk1 = E1 + oy[2*j+1];
            O.z = fmaf(c00,xk0,c01*xk1); O.w = fmaf(c10,xk0,c11*xk1);
            { float n0=fmaf(t00,E0,t01*E1), n1=fmaf(t10,E0,t11*E1); E0=n0; E1=n1; }
            orow[j] = O;
        }
    }
    __syncwarp();

    // ---- coalesced streaming store of the 2KB warp out tile ----
    float4* q4 = (float4*)out + (size_t)warpStepBase/2;
    #pragma unroll
    for (int i=0;i<4;i++){
        int q = lane + 32*i;
        __stcs(q4+q, sout4[(q>>3)*9 + (q&7)]);
    }
}

// --------------------------------------------------------------- launch ----
extern "C" void kernel_launch(void* const* d_in, const int* in_sizes, int n_in,
                              void* d_out, int out_size)
{
    const float* in  = (const float*)d_in[0];
    const float* A   = (const float*)d_in[1];
    const float* B   = (const float*)d_in[2];
    // d_in[3] = D (unused by the reference)
    const float* E   = (const float*)d_in[4];
    const float* cov = (const float*)d_in[5];
    const float* tp  = (const float*)d_in[6];
    const float* ini = (const float*)d_in[7];
    float* out = (float*)d_out;

    cudaFuncSetAttribute(k_pass3, cudaFuncAttributeMaxDynamicSharedMemorySize, P3_SMEM);

    k_setup<<<1,1>>>(A,B,E,cov,tp,ini);
    k_pass1<<<NCTA,TPB>>>(in);
    k_pass2<<<1,1024>>>();
    k_pass3<<<NCTA,TPB,P3_SMEM>>>(in, out);
}